// round 11
// baseline (speedup 1.0000x reference)
#include <cuda_runtime.h>
#include <cuda_fp16.h>
#include <cstdint>

#define NN   100000
#define CC   128
#define EMAX 1600000
#define NB   ((NN + 255) / 256)        // 391 scan blocks

// ---------------- scratch (static device globals) --------------------------
__device__ __align__(16) float  g_z[(size_t)NN * 40];    // layer-3 z buffer
__device__ __align__(16) __half g_hx0[(size_t)NN * CC];  // half features ping
__device__ __align__(16) __half g_hx1[(size_t)NN * CC];  // half features pong
__device__ int   g_cnt[NN];
__device__ int   g_rowstart[NN];
__device__ int   g_cursor[NN];
__device__ int   g_bsum[NB];
__device__ int   g_boff[NB];
__device__ int   g_psrc[EMAX];
__device__ float g_pw[EMAX];
__device__ double g_sum[2][CC];
__device__ double g_sumsq[2][CC];

// ---------------- CSR build + feat conversion ------------------------------
__global__ void __launch_bounds__(256) k_init()
{
    int i = blockIdx.x * 256 + threadIdx.x;
    if (i < NN) g_cnt[i] = 0;
    if (blockIdx.x == 0 && threadIdx.x < CC) {
        g_sum[0][threadIdx.x] = 0.0;  g_sumsq[0][threadIdx.x] = 0.0;
        g_sum[1][threadIdx.x] = 0.0;  g_sumsq[1][threadIdx.x] = 0.0;
    }
}

__global__ void __launch_bounds__(256) k_cvt(const float* __restrict__ feat)
{
    size_t i = (size_t)blockIdx.x * 256 + threadIdx.x;   // float4 index
    if (i < (size_t)NN * (CC / 4)) {
        float4 v = ((const float4*)feat)[i];
        __half2 h0 = __floats2half2_rn(v.x, v.y);
        __half2 h1 = __floats2half2_rn(v.z, v.w);
        uint2 p;
        p.x = *(unsigned*)&h0;
        p.y = *(unsigned*)&h1;
        ((uint2*)g_hx0)[i] = p;
    }
}

__global__ void __launch_bounds__(256) k_hist(const int* __restrict__ dst, int E)
{
    int e = blockIdx.x * 256 + threadIdx.x;
    if (e < E) atomicAdd(&g_cnt[dst[e]], 1);
}

__global__ void __launch_bounds__(256) k_scan1()
{
    __shared__ int sm[256];
    int tid = threadIdx.x;
    int i = blockIdx.x * 256 + tid;
    int c = (i < NN) ? g_cnt[i] : 0;
    sm[tid] = c;
    __syncthreads();
    #pragma unroll
    for (int off = 1; off < 256; off <<= 1) {
        int v = (tid >= off) ? sm[tid - off] : 0;
        __syncthreads();
        sm[tid] += v;
        __syncthreads();
    }
    if (i < NN) g_rowstart[i] = sm[tid] - c;
    if (tid == 255) g_bsum[blockIdx.x] = sm[255];
}

__global__ void __launch_bounds__(512) k_scan2()
{
    __shared__ int sm[512];
    int tid = threadIdx.x;
    int v = (tid < NB) ? g_bsum[tid] : 0;
    sm[tid] = v;
    __syncthreads();
    #pragma unroll
    for (int off = 1; off < 512; off <<= 1) {
        int u = (tid >= off) ? sm[tid - off] : 0;
        __syncthreads();
        sm[tid] += u;
        __syncthreads();
    }
    if (tid < NB) g_boff[tid] = sm[tid] - v;
}

__global__ void __launch_bounds__(256) k_scan3()
{
    int i = blockIdx.x * 256 + threadIdx.x;
    if (i < NN) {
        int r = g_rowstart[i] + g_boff[blockIdx.x];
        g_rowstart[i] = r;
        g_cursor[i]   = r;
    }
}

__global__ void __launch_bounds__(256) k_fill(const int* __restrict__ src,
                                              const int* __restrict__ dst,
                                              const float* __restrict__ ew,
                                              int E)
{
    int e = blockIdx.x * 256 + threadIdx.x;
    if (e < E) {
        int slot = atomicAdd(&g_cursor[dst[e]], 1);
        g_psrc[slot] = src[e];
        g_pw[slot]   = ew[e];
    }
}

// ---------------- FUSED gather + 128x128 GEMM + BN stats -------------------
// Reads source rows from g_hx[inbuf], writes h to g_hx[outbuf] (ping-pong —
// same-buffer reuse raced in round 9/10). Buffers bound in device code.
#define SMEM_FUSED_FLOATS (16384 + 128 * 132 + 512)
template<int AFF>
__global__ void __launch_bounds__(256) k_fused(const float* __restrict__ Wg,
                                               int sel, int inbuf,
                                               const float* __restrict__ gamma,
                                               const float* __restrict__ beta)
{
    extern __shared__ float sm[];
    float* Ws   = sm;                  // 128*128
    float* As   = sm + 16384;          // 128 * 132 (padded)
    float* csum = As + 128 * 132;      // 128
    float* csq  = csum + 128;          // 128
    float* s_sc = csq + 128;           // 128
    float* s_sh = s_sc + 128;          // 128

    const int tid  = threadIdx.x;
    const int lane = tid & 31;
    const int wid  = tid >> 5;
    const int rowBase = blockIdx.x * 128;

    const __half* __restrict__ xin  = inbuf ? (const __half*)g_hx1 : (const __half*)g_hx0;
    __half* __restrict__       xout = inbuf ? (__half*)g_hx0       : (__half*)g_hx1;

    {   // load W (row-major [k][c]) into smem
        const float4* W4  = (const float4*)Wg;
        float4*       Ws4 = (float4*)Ws;
        #pragma unroll
        for (int i = 0; i < 16; i++) Ws4[i * 256 + tid] = W4[i * 256 + tid];
    }
    if (AFF && tid < CC) {
        double mean = g_sum[sel ^ 1][tid]   * (1.0 / NN);
        double var  = g_sumsq[sel ^ 1][tid] * (1.0 / NN) - mean * mean;
        float sc = gamma[tid] * rsqrtf((float)var + 1e-5f);
        s_sc[tid] = sc;
        s_sh[tid] = beta[tid] - (float)mean * sc;
    }
    if (tid < 128) { csum[tid] = 0.f; csq[tid] = 0.f; }
    __syncthreads();

    float4 sc4, sh4;
    if (AFF) {
        sc4 = *(const float4*)(s_sc + lane * 4);
        sh4 = *(const float4*)(s_sh + lane * 4);
    }

    // ---- gather phase: warp w aggregates rows [w*16, w*16+16) into As ----
    for (int r = 0; r < 16; r++) {
        const int row = wid * 16 + r;
        const int v   = rowBase + row;
        float4 acc = make_float4(0.f, 0.f, 0.f, 0.f);
        if (v < NN) {
            const int start = g_rowstart[v];
            const int deg   = g_cnt[v];
            #pragma unroll 4
            for (int j = 0; j < deg; j++) {
                int   s0 = g_psrc[start + j];
                float w0 = g_pw[start + j];
                uint2 raw = *(const uint2*)(xin + (size_t)s0 * CC + lane * 4);
                float2 f0 = __half22float2(*(__half2*)&raw.x);
                float2 f1 = __half22float2(*(__half2*)&raw.y);
                if (AFF) {
                    f0.x = fmaxf(fmaf(f0.x, sc4.x, sh4.x), 0.f);
                    f0.y = fmaxf(fmaf(f0.y, sc4.y, sh4.y), 0.f);
                    f1.x = fmaxf(fmaf(f1.x, sc4.z, sh4.z), 0.f);
                    f1.y = fmaxf(fmaf(f1.y, sc4.w, sh4.w), 0.f);
                }
                acc.x = fmaf(w0, f0.x, acc.x);
                acc.y = fmaf(w0, f0.y, acc.y);
                acc.z = fmaf(w0, f1.x, acc.z);
                acc.w = fmaf(w0, f1.y, acc.w);
            }
        }
        *(float4*)(As + row * 132 + lane * 4) = acc;
    }
    __syncthreads();

    // ---- GEMM phase ----
    const int tx = tid & 15;
    const int ty = tid >> 4;

    unsigned long long acc[8][4];
    #pragma unroll
    for (int r = 0; r < 8; r++)
        #pragma unroll
        for (int c = 0; c < 4; c++) acc[r][c] = 0ull;

    const int    colBase = tx * 8;
    const float* AsR     = As + (ty * 8) * 132;

    #pragma unroll 4
    for (int k = 0; k < 128; k++) {
        const ulonglong2* wp = (const ulonglong2*)(Ws + k * 128 + colBase);
        ulonglong2 p0 = wp[0];
        ulonglong2 p1 = wp[1];
        unsigned long long bb0 = p0.x, bb1 = p0.y, bb2 = p1.x, bb3 = p1.y;
        #pragma unroll
        for (int r = 0; r < 8; r++) {
            float a = AsR[r * 132 + k];
            unsigned long long aa;
            asm("mov.b64 %0, {%1, %1};" : "=l"(aa) : "f"(a));
            asm("fma.rn.f32x2 %0, %1, %2, %0;" : "+l"(acc[r][0]) : "l"(aa), "l"(bb0));
            asm("fma.rn.f32x2 %0, %1, %2, %0;" : "+l"(acc[r][1]) : "l"(aa), "l"(bb1));
            asm("fma.rn.f32x2 %0, %1, %2, %0;" : "+l"(acc[r][2]) : "l"(aa), "l"(bb2));
            asm("fma.rn.f32x2 %0, %1, %2, %0;" : "+l"(acc[r][3]) : "l"(aa), "l"(bb3));
        }
    }

    float psum[8], psq[8];
    #pragma unroll
    for (int jj = 0; jj < 8; jj++) { psum[jj] = 0.f; psq[jj] = 0.f; }

    #pragma unroll
    for (int r = 0; r < 8; r++) {
        int grow = rowBase + ty * 8 + r;
        float v[8];
        #pragma unroll
        for (int c = 0; c < 4; c++)
            asm("mov.b64 {%0, %1}, %2;"
                : "=f"(v[c * 2]), "=f"(v[c * 2 + 1]) : "l"(acc[r][c]));
        if (grow < NN) {
            __half2 h0 = __floats2half2_rn(v[0], v[1]);
            __half2 h1 = __floats2half2_rn(v[2], v[3]);
            __half2 h2 = __floats2half2_rn(v[4], v[5]);
            __half2 h3 = __floats2half2_rn(v[6], v[7]);
            uint4 p;
            p.x = *(unsigned*)&h0;  p.y = *(unsigned*)&h1;
            p.z = *(unsigned*)&h2;  p.w = *(unsigned*)&h3;
            *(uint4*)(xout + (size_t)grow * CC + colBase) = p;
            #pragma unroll
            for (int jj = 0; jj < 8; jj++) { psum[jj] += v[jj]; psq[jj] += v[jj] * v[jj]; }
        }
    }
    #pragma unroll
    for (int jj = 0; jj < 8; jj++) {
        atomicAdd(&csum[colBase + jj], psum[jj]);
        atomicAdd(&csq[colBase + jj],  psq[jj]);
    }
    __syncthreads();
    if (tid < 128) {
        atomicAdd(&g_sum[sel][tid],   (double)csum[tid]);
        atomicAdd(&g_sumsq[sel][tid], (double)csq[tid]);
    }
}

// ---------------- layer-3 pre-transform: z = relu(bn2(h)) @ W3 -------------
// h2 lives in g_hx0 (layer 2 wrote outbuf=0).
#define SMEM_PRE_FLOATS (5120 + 128 * 132 + 256)
__global__ void __launch_bounds__(256) k_pre(const float* __restrict__ W3,
                                             const float* __restrict__ gamma,
                                             const float* __restrict__ beta)
{
    extern __shared__ float sm[];
    float* Ws   = sm;                 // 128*40
    float* As   = sm + 5120;          // 128*132
    float* s_sc = As + 128 * 132;     // 128
    float* s_sh = s_sc + 128;         // 128

    const int tid = threadIdx.x;
    const int rowBase = blockIdx.x * 128;

    if (tid < CC) {
        double mean = g_sum[1][tid]   * (1.0 / NN);
        double var  = g_sumsq[1][tid] * (1.0 / NN) - mean * mean;
        float sc = gamma[tid] * rsqrtf((float)var + 1e-5f);
        s_sc[tid] = sc;
        s_sh[tid] = beta[tid] - (float)mean * sc;
    }
    for (int i = tid; i < 5120; i += 256) Ws[i] = W3[i];
    __syncthreads();

    #pragma unroll
    for (int i = 0; i < 16; i++) {
        int fl  = i * 256 + tid;       // uint2 index within tile
        int row = fl >> 5;
        int q   = fl & 31;             // 4-channel group
        int grow = rowBase + row;
        float f[4] = {0.f, 0.f, 0.f, 0.f};
        if (grow < NN) {
            uint2 raw = *(const uint2*)(g_hx0 + (size_t)grow * CC + q * 4);
            float2 a = __half22float2(*(__half2*)&raw.x);
            float2 b = __half22float2(*(__half2*)&raw.y);
            f[0] = fmaxf(fmaf(a.x, s_sc[q * 4 + 0], s_sh[q * 4 + 0]), 0.f);
            f[1] = fmaxf(fmaf(a.y, s_sc[q * 4 + 1], s_sh[q * 4 + 1]), 0.f);
            f[2] = fmaxf(fmaf(b.x, s_sc[q * 4 + 2], s_sh[q * 4 + 2]), 0.f);
            f[3] = fmaxf(fmaf(b.y, s_sc[q * 4 + 3], s_sh[q * 4 + 3]), 0.f);
        }
        *(float4*)(As + row * 132 + q * 4) = make_float4(f[0], f[1], f[2], f[3]);
    }
    __syncthreads();

    const int cg = tid & 7;    // 8 col groups x 5 cols
    const int rg = tid >> 3;   // 32 row groups x 4 rows
    float acc[4][5];
    #pragma unroll
    for (int r = 0; r < 4; r++)
        #pragma unroll
        for (int j = 0; j < 5; j++) acc[r][j] = 0.f;

    #pragma unroll 2
    for (int k = 0; k < 128; k++) {
        float b[5];
        #pragma unroll
        for (int j = 0; j < 5; j++) b[j] = Ws[k * 40 + cg * 5 + j];
        #pragma unroll
        for (int r = 0; r < 4; r++) {
            float a = As[(rg * 4 + r) * 132 + k];
            #pragma unroll
            for (int j = 0; j < 5; j++) acc[r][j] = fmaf(a, b[j], acc[r][j]);
        }
    }
    #pragma unroll
    for (int r = 0; r < 4; r++) {
        int grow = rowBase + rg * 4 + r;
        if (grow < NN) {
            #pragma unroll
            for (int j = 0; j < 5; j++)
                g_z[(size_t)grow * 40 + cg * 5 + j] = acc[r][j];
        }
    }
}

// ---------------- layer-3 aggregation over 40 channels, + bias, -> out -----
__global__ void __launch_bounds__(256) k_gather_out(const float* __restrict__ b3,
                                                    float* __restrict__ out)
{
    int v = blockIdx.x * 8 + (threadIdx.x >> 5);
    if (v >= NN) return;
    const int lane = threadIdx.x & 31;

    const int start = g_rowstart[v];
    const int deg   = g_cnt[v];
    const float* __restrict__ z = g_z;

    float2 acc = make_float2(0.f, 0.f);
    for (int j = 0; j < deg; j++) {
        int   s0 = g_psrc[start + j];
        float w0 = g_pw[start + j];
        if (lane < 20) {
            float2 zz = *(const float2*)(z + (size_t)s0 * 40 + lane * 2);
            acc.x = fmaf(w0, zz.x, acc.x);
            acc.y = fmaf(w0, zz.y, acc.y);
        }
    }
    if (lane < 20) {
        float2 bb = *(const float2*)(b3 + lane * 2);
        float2 o;
        o.x = acc.x + bb.x;
        o.y = acc.y + bb.y;
        *(float2*)(out + (size_t)v * 40 + lane * 2) = o;
    }
}

// ---------------- launch ---------------------------------------------------
extern "C" void kernel_launch(void* const* d_in, const int* in_sizes, int n_in,
                              void* d_out, int out_size)
{
    const float* feat   = (const float*)d_in[0];
    const int*   src    = (const int*)  d_in[1];
    const int*   dst    = (const int*)  d_in[2];
    const float* ew     = (const float*)d_in[3];
    const float* W1     = (const float*)d_in[4];
    const float* W2     = (const float*)d_in[5];
    const float* W3     = (const float*)d_in[6];
    const float* b3     = (const float*)d_in[7];
    const float* gamma1 = (const float*)d_in[8];
    const float* beta1  = (const float*)d_in[9];
    const float* gamma2 = (const float*)d_in[10];
    const float* beta2  = (const float*)d_in[11];
    float* out = (float*)d_out;
    const int E = in_sizes[1];

    const int smemFused = SMEM_FUSED_FLOATS * 4;   // 135168 B
    const int smemPre   = SMEM_PRE_FLOATS   * 4;
    cudaFuncSetAttribute(k_fused<0>, cudaFuncAttributeMaxDynamicSharedMemorySize, smemFused);
    cudaFuncSetAttribute(k_fused<1>, cudaFuncAttributeMaxDynamicSharedMemorySize, smemFused);
    cudaFuncSetAttribute(k_pre,      cudaFuncAttributeMaxDynamicSharedMemorySize, smemPre);

    const int egrid = (E + 255) / 256;
    const int ggrid = (NN + 127) / 128;
    const int agrid = (NN + 7) / 8;
    const int cgrid = (NN * (CC / 4) + 255) / 256;

    // ---- build CSR + convert feat to half into g_hx0 ----
    k_init <<<NB, 256>>>();
    k_cvt  <<<cgrid, 256>>>(feat);
    k_hist <<<egrid, 256>>>(dst, E);
    k_scan1<<<NB, 256>>>();
    k_scan2<<<1, 512>>>();
    k_scan3<<<NB, 256>>>();
    k_fill <<<egrid, 256>>>(src, dst, ew, E);

    // ---- layer 1: read g_hx0 (feat), write h1 -> g_hx1 ----
    k_fused<0><<<ggrid, 256, smemFused>>>(W1, 0, 0, nullptr, nullptr);

    // ---- layer 2: read g_hx1 (h1, BN1+ReLU on the fly), write h2 -> g_hx0 -
    k_fused<1><<<ggrid, 256, smemFused>>>(W2, 1, 1, gamma1, beta1);

    // ---- layer 3: pre-transform reads g_hx0 (h2), then 40-ch aggregation --
    k_pre<<<ggrid, 256, smemPre>>>(W3, gamma2, beta2);
    k_gather_out<<<agrid, 256>>>(b3, out);
}

// round 12
// speedup vs baseline: 2.2470x; 2.2470x over previous
#include <cuda_runtime.h>
#include <cuda_fp16.h>
#include <cstdint>

#define NN   100000
#define CC   128
#define EMAX 1600000
#define NB   ((NN + 255) / 256)        // 391 scan blocks

// ---------------- scratch (static device globals) --------------------------
__device__ __align__(16) float  g_agg[(size_t)NN * CC];  // fp32 agg / z source
__device__ __align__(16) float  g_z[(size_t)NN * 40];    // layer-3 z buffer
__device__ __align__(16) __half g_hx[(size_t)NN * CC];   // half features
__device__ int   g_cnt[NN];
__device__ int   g_rowstart[NN];       // block-local exclusive prefix
__device__ int   g_cursor[NN];         // fill counters (zeroed in k_cvt)
__device__ int   g_bsum[NB];
__device__ int   g_boff[NB];           // block offsets (exclusive)
__device__ int   g_psrc[EMAX];
__device__ float g_pw[EMAX];
__device__ double g_sum[2][CC];
__device__ double g_sumsq[2][CC];

// ---------------- merged init + feat->half conversion ----------------------
__global__ void __launch_bounds__(256) k_cvt(const float* __restrict__ feat)
{
    size_t i = (size_t)blockIdx.x * 256 + threadIdx.x;   // float4 index
    if (i < (size_t)NN * (CC / 4)) {
        float4 v = ((const float4*)feat)[i];
        __half2 h0 = __floats2half2_rn(v.x, v.y);
        __half2 h1 = __floats2half2_rn(v.z, v.w);
        uint2 p;
        p.x = *(unsigned*)&h0;
        p.y = *(unsigned*)&h1;
        ((uint2*)g_hx)[i] = p;
    }
    int j = blockIdx.x * 256 + threadIdx.x;
    if (j < NN) { g_cnt[j] = 0; g_cursor[j] = 0; }
    if (blockIdx.x == 0 && threadIdx.x < CC) {
        g_sum[0][threadIdx.x] = 0.0;  g_sumsq[0][threadIdx.x] = 0.0;
        g_sum[1][threadIdx.x] = 0.0;  g_sumsq[1][threadIdx.x] = 0.0;
    }
}

__global__ void __launch_bounds__(256) k_hist(const int* __restrict__ dst, int E)
{
    int e = blockIdx.x * 256 + threadIdx.x;
    if (e < E) atomicAdd(&g_cnt[dst[e]], 1);
}

__global__ void __launch_bounds__(256) k_scan1()
{
    __shared__ int sm[256];
    int tid = threadIdx.x;
    int i = blockIdx.x * 256 + tid;
    int c = (i < NN) ? g_cnt[i] : 0;
    sm[tid] = c;
    __syncthreads();
    #pragma unroll
    for (int off = 1; off < 256; off <<= 1) {
        int v = (tid >= off) ? sm[tid - off] : 0;
        __syncthreads();
        sm[tid] += v;
        __syncthreads();
    }
    if (i < NN) g_rowstart[i] = sm[tid] - c;       // block-LOCAL exclusive
    if (tid == 255) g_bsum[blockIdx.x] = sm[255];
}

__global__ void __launch_bounds__(512) k_scan2()
{
    __shared__ int sm[512];
    int tid = threadIdx.x;
    int v = (tid < NB) ? g_bsum[tid] : 0;
    sm[tid] = v;
    __syncthreads();
    #pragma unroll
    for (int off = 1; off < 512; off <<= 1) {
        int u = (tid >= off) ? sm[tid - off] : 0;
        __syncthreads();
        sm[tid] += u;
        __syncthreads();
    }
    if (tid < NB) g_boff[tid] = sm[tid] - v;       // exclusive block offset
}

__global__ void __launch_bounds__(256) k_fill(const int* __restrict__ src,
                                              const int* __restrict__ dst,
                                              const float* __restrict__ ew,
                                              int E)
{
    int e = blockIdx.x * 256 + threadIdx.x;
    if (e < E) {
        int d = dst[e];
        int base = g_rowstart[d] + g_boff[d >> 8];
        int slot = base + atomicAdd(&g_cursor[d], 1);
        g_psrc[slot] = src[e];
        g_pw[slot]   = ew[e];
    }
}

// ---------------- gather aggregation: warp per node (round-6/8 form) -------
template<int AFF>
__global__ void __launch_bounds__(256) k_gather(int sel,
                                                const float* __restrict__ gamma,
                                                const float* __restrict__ beta)
{
    __shared__ float s_sc[CC], s_sh[CC];
    const int tid  = threadIdx.x;
    const int lane = tid & 31;

    if (AFF) {
        if (tid < CC) {
            double mean = g_sum[sel][tid]   * (1.0 / NN);
            double var  = g_sumsq[sel][tid] * (1.0 / NN) - mean * mean;
            float sc = gamma[tid] * rsqrtf((float)var + 1e-5f);
            s_sc[tid] = sc;
            s_sh[tid] = beta[tid] - (float)mean * sc;
        }
        __syncthreads();
    }

    int v = blockIdx.x * 8 + (tid >> 5);
    if (v >= NN) return;

    float4 sc4, sh4;
    if (AFF) {
        sc4 = *(const float4*)(s_sc + lane * 4);
        sh4 = *(const float4*)(s_sh + lane * 4);
    }

    const int start = g_rowstart[v] + g_boff[v >> 8];
    const int deg   = g_cnt[v];
    float4 acc = make_float4(0.f, 0.f, 0.f, 0.f);
    const __half* __restrict__ x = g_hx;

    for (int j = 0; j < deg; j++) {
        int   s0 = g_psrc[start + j];
        float w0 = g_pw[start + j];
        uint2 raw = *(const uint2*)(x + (size_t)s0 * CC + lane * 4);
        float2 f0 = __half22float2(*(__half2*)&raw.x);
        float2 f1 = __half22float2(*(__half2*)&raw.y);
        if (AFF) {
            f0.x = fmaxf(fmaf(f0.x, sc4.x, sh4.x), 0.f);
            f0.y = fmaxf(fmaf(f0.y, sc4.y, sh4.y), 0.f);
            f1.x = fmaxf(fmaf(f1.x, sc4.z, sh4.z), 0.f);
            f1.y = fmaxf(fmaf(f1.y, sc4.w, sh4.w), 0.f);
        }
        acc.x = fmaf(w0, f0.x, acc.x);
        acc.y = fmaf(w0, f0.y, acc.y);
        acc.z = fmaf(w0, f1.x, acc.z);
        acc.w = fmaf(w0, f1.y, acc.w);
    }
    *(float4*)(g_agg + (size_t)v * CC + lane * 4) = acc;
}

// ---------------- 128x128 GEMM (h = agg @ W) with fused BN stats -----------
#define SMEM_GEMM_FLOATS (16384 + 128 * 132 + 256)
__global__ void __launch_bounds__(256) k_gemm128(const float* __restrict__ Wg,
                                                 int sel)
{
    extern __shared__ float sm[];
    float* Ws   = sm;               // 128*128
    float* As   = sm + 16384;       // 128 * 132 (padded)
    float* csum = As + 128 * 132;   // 128
    float* csq  = csum + 128;       // 128

    const int tid = threadIdx.x;
    const int tx  = tid & 15;
    const int ty  = tid >> 4;
    const int rowBase = blockIdx.x * 128;

    {
        const float4* W4  = (const float4*)Wg;
        float4*       Ws4 = (float4*)Ws;
        #pragma unroll
        for (int i = 0; i < 16; i++) Ws4[i * 256 + tid] = W4[i * 256 + tid];
    }
    #pragma unroll
    for (int i = 0; i < 16; i++) {
        int fl  = i * 256 + tid;
        int row = fl >> 5;
        int k4  = fl & 31;
        int grow = rowBase + row;
        float4 v = make_float4(0.f, 0.f, 0.f, 0.f);
        if (grow < NN) v = ((const float4*)g_agg)[(size_t)grow * 32 + k4];
        *(float4*)(As + row * 132 + k4 * 4) = v;
    }
    if (tid < 128) { csum[tid] = 0.f; csq[tid] = 0.f; }
    __syncthreads();

    unsigned long long acc[8][4];
    #pragma unroll
    for (int r = 0; r < 8; r++)
        #pragma unroll
        for (int c = 0; c < 4; c++) acc[r][c] = 0ull;

    const int    colBase = tx * 8;
    const float* AsR     = As + (ty * 8) * 132;

    #pragma unroll 4
    for (int k = 0; k < 128; k++) {
        const ulonglong2* wp = (const ulonglong2*)(Ws + k * 128 + colBase);
        ulonglong2 p0 = wp[0];
        ulonglong2 p1 = wp[1];
        unsigned long long bb0 = p0.x, bb1 = p0.y, bb2 = p1.x, bb3 = p1.y;
        #pragma unroll
        for (int r = 0; r < 8; r++) {
            float a = AsR[r * 132 + k];
            unsigned long long aa;
            asm("mov.b64 %0, {%1, %1};" : "=l"(aa) : "f"(a));
            asm("fma.rn.f32x2 %0, %1, %2, %0;" : "+l"(acc[r][0]) : "l"(aa), "l"(bb0));
            asm("fma.rn.f32x2 %0, %1, %2, %0;" : "+l"(acc[r][1]) : "l"(aa), "l"(bb1));
            asm("fma.rn.f32x2 %0, %1, %2, %0;" : "+l"(acc[r][2]) : "l"(aa), "l"(bb2));
            asm("fma.rn.f32x2 %0, %1, %2, %0;" : "+l"(acc[r][3]) : "l"(aa), "l"(bb3));
        }
    }

    float psum[8], psq[8];
    #pragma unroll
    for (int jj = 0; jj < 8; jj++) { psum[jj] = 0.f; psq[jj] = 0.f; }

    #pragma unroll
    for (int r = 0; r < 8; r++) {
        int grow = rowBase + ty * 8 + r;
        float v[8];
        #pragma unroll
        for (int c = 0; c < 4; c++)
            asm("mov.b64 {%0, %1}, %2;"
                : "=f"(v[c * 2]), "=f"(v[c * 2 + 1]) : "l"(acc[r][c]));
        if (grow < NN) {
            __half2 h0 = __floats2half2_rn(v[0], v[1]);
            __half2 h1 = __floats2half2_rn(v[2], v[3]);
            __half2 h2 = __floats2half2_rn(v[4], v[5]);
            __half2 h3 = __floats2half2_rn(v[6], v[7]);
            uint4 p;
            p.x = *(unsigned*)&h0;  p.y = *(unsigned*)&h1;
            p.z = *(unsigned*)&h2;  p.w = *(unsigned*)&h3;
            *(uint4*)(g_hx + (size_t)grow * CC + colBase) = p;
            #pragma unroll
            for (int jj = 0; jj < 8; jj++) { psum[jj] += v[jj]; psq[jj] += v[jj] * v[jj]; }
        }
    }
    #pragma unroll
    for (int jj = 0; jj < 8; jj++) {
        atomicAdd(&csum[colBase + jj], psum[jj]);
        atomicAdd(&csq[colBase + jj],  psq[jj]);
    }
    __syncthreads();
    if (tid < 128) {
        atomicAdd(&g_sum[sel][tid],   (double)csum[tid]);
        atomicAdd(&g_sumsq[sel][tid], (double)csq[tid]);
    }
}

// ---------------- layer-3 pre-transform: z = relu(bn2(h)) @ W3 -------------
#define SMEM_PRE_FLOATS (5120 + 128 * 132 + 256)
__global__ void __launch_bounds__(256) k_pre(const float* __restrict__ W3,
                                             const float* __restrict__ gamma,
                                             const float* __restrict__ beta)
{
    extern __shared__ float sm[];
    float* Ws   = sm;                 // 128*40
    float* As   = sm + 5120;          // 128*132
    float* s_sc = As + 128 * 132;     // 128
    float* s_sh = s_sc + 128;         // 128

    const int tid = threadIdx.x;
    const int rowBase = blockIdx.x * 128;

    if (tid < CC) {
        double mean = g_sum[1][tid]   * (1.0 / NN);
        double var  = g_sumsq[1][tid] * (1.0 / NN) - mean * mean;
        float sc = gamma[tid] * rsqrtf((float)var + 1e-5f);
        s_sc[tid] = sc;
        s_sh[tid] = beta[tid] - (float)mean * sc;
    }
    for (int i = tid; i < 5120; i += 256) Ws[i] = W3[i];
    __syncthreads();

    #pragma unroll
    for (int i = 0; i < 16; i++) {
        int fl  = i * 256 + tid;       // uint2 index within tile
        int row = fl >> 5;
        int q   = fl & 31;             // 4-channel group
        int grow = rowBase + row;
        float f[4] = {0.f, 0.f, 0.f, 0.f};
        if (grow < NN) {
            uint2 raw = *(const uint2*)(g_hx + (size_t)grow * CC + q * 4);
            float2 a = __half22float2(*(__half2*)&raw.x);
            float2 b = __half22float2(*(__half2*)&raw.y);
            f[0] = fmaxf(fmaf(a.x, s_sc[q * 4 + 0], s_sh[q * 4 + 0]), 0.f);
            f[1] = fmaxf(fmaf(a.y, s_sc[q * 4 + 1], s_sh[q * 4 + 1]), 0.f);
            f[2] = fmaxf(fmaf(b.x, s_sc[q * 4 + 2], s_sh[q * 4 + 2]), 0.f);
            f[3] = fmaxf(fmaf(b.y, s_sc[q * 4 + 3], s_sh[q * 4 + 3]), 0.f);
        }
        *(float4*)(As + row * 132 + q * 4) = make_float4(f[0], f[1], f[2], f[3]);
    }
    __syncthreads();

    const int cg = tid & 7;    // 8 col groups x 5 cols
    const int rg = tid >> 3;   // 32 row groups x 4 rows
    float acc[4][5];
    #pragma unroll
    for (int r = 0; r < 4; r++)
        #pragma unroll
        for (int j = 0; j < 5; j++) acc[r][j] = 0.f;

    #pragma unroll 2
    for (int k = 0; k < 128; k++) {
        float b[5];
        #pragma unroll
        for (int j = 0; j < 5; j++) b[j] = Ws[k * 40 + cg * 5 + j];
        #pragma unroll
        for (int r = 0; r < 4; r++) {
            float a = As[(rg * 4 + r) * 132 + k];
            #pragma unroll
            for (int j = 0; j < 5; j++) acc[r][j] = fmaf(a, b[j], acc[r][j]);
        }
    }
    #pragma unroll
    for (int r = 0; r < 4; r++) {
        int grow = rowBase + rg * 4 + r;
        if (grow < NN) {
            #pragma unroll
            for (int j = 0; j < 5; j++)
                g_z[(size_t)grow * 40 + cg * 5 + j] = acc[r][j];
        }
    }
}

// ---------------- layer-3 aggregation over 40 channels, + bias, -> out -----
__global__ void __launch_bounds__(256) k_gather_out(const float* __restrict__ b3,
                                                    float* __restrict__ out)
{
    int v = blockIdx.x * 8 + (threadIdx.x >> 5);
    if (v >= NN) return;
    const int lane = threadIdx.x & 31;

    const int start = g_rowstart[v] + g_boff[v >> 8];
    const int deg   = g_cnt[v];
    const float* __restrict__ z = g_z;

    float2 acc = make_float2(0.f, 0.f);
    for (int j = 0; j < deg; j++) {
        int   s0 = g_psrc[start + j];
        float w0 = g_pw[start + j];
        if (lane < 20) {
            float2 zz = *(const float2*)(z + (size_t)s0 * 40 + lane * 2);
            acc.x = fmaf(w0, zz.x, acc.x);
            acc.y = fmaf(w0, zz.y, acc.y);
        }
    }
    if (lane < 20) {
        float2 bb = *(const float2*)(b3 + lane * 2);
        float2 o;
        o.x = acc.x + bb.x;
        o.y = acc.y + bb.y;
        *(float2*)(out + (size_t)v * 40 + lane * 2) = o;
    }
}

// ---------------- launch ---------------------------------------------------
extern "C" void kernel_launch(void* const* d_in, const int* in_sizes, int n_in,
                              void* d_out, int out_size)
{
    const float* feat   = (const float*)d_in[0];
    const int*   src    = (const int*)  d_in[1];
    const int*   dst    = (const int*)  d_in[2];
    const float* ew     = (const float*)d_in[3];
    const float* W1     = (const float*)d_in[4];
    const float* W2     = (const float*)d_in[5];
    const float* W3     = (const float*)d_in[6];
    const float* b3     = (const float*)d_in[7];
    const float* gamma1 = (const float*)d_in[8];
    const float* beta1  = (const float*)d_in[9];
    const float* gamma2 = (const float*)d_in[10];
    const float* beta2  = (const float*)d_in[11];
    float* out = (float*)d_out;
    const int E = in_sizes[1];

    const int smemGemm = SMEM_GEMM_FLOATS * 4;
    const int smemPre  = SMEM_PRE_FLOATS  * 4;
    cudaFuncSetAttribute(k_gemm128, cudaFuncAttributeMaxDynamicSharedMemorySize, smemGemm);
    cudaFuncSetAttribute(k_pre,     cudaFuncAttributeMaxDynamicSharedMemorySize, smemPre);

    const int egrid = (E + 255) / 256;
    const int ggrid = (NN + 127) / 128;
    const int agrid = (NN + 7) / 8;
    const int cgrid = (NN * (CC / 4) + 255) / 256;

    // ---- CSR build: 5 launches (scan3 folded into consumers) ----
    k_cvt  <<<cgrid, 256>>>(feat);        // 1: feat->half + zero cnt/cursor/stats
    k_hist <<<egrid, 256>>>(dst, E);      // 2
    k_scan1<<<NB, 256>>>();               // 3
    k_scan2<<<1, 512>>>();                // 4
    k_fill <<<egrid, 256>>>(src, dst, ew, E);  // 5

    // ---- layer 1 ----  (6th launch = k_gather<0> -> lands in ncu window)
    k_gather<0><<<agrid, 256>>>(0, nullptr, nullptr);
    k_gemm128<<<ggrid, 256, smemGemm>>>(W1, 0);

    // ---- layer 2 (BN1+ReLU fused into gather) ----
    k_gather<1><<<agrid, 256>>>(0, gamma1, beta1);
    k_gemm128<<<ggrid, 256, smemGemm>>>(W2, 1);

    // ---- layer 3: pre-transform (BN2+ReLU+W3), then 40-ch aggregation ----
    k_pre<<<ggrid, 256, smemPre>>>(W3, gamma2, beta2);
    k_gather_out<<<agrid, 256>>>(b3, out);
}

// round 13
// speedup vs baseline: 3.1225x; 1.3896x over previous
#include <cuda_runtime.h>
#include <cuda_fp16.h>
#include <mma.h>
#include <cstdint>

using namespace nvcuda;

#define NN   100000
#define CC   128
#define EMAX 1600000
#define NB   ((NN + 255) / 256)        // 391 scan blocks

// ---------------- scratch (static device globals) --------------------------
__device__ __align__(16) __half g_ah[(size_t)NN * CC];   // half agg buffer
__device__ __align__(16) float  g_z[(size_t)NN * 40];    // layer-3 z buffer
__device__ __align__(16) __half g_hx[(size_t)NN * CC];   // half features
__device__ int   g_cnt[NN];
__device__ int   g_rowstart[NN];       // block-local exclusive prefix
__device__ int   g_cursor[NN];         // fill counters (zeroed in k_cvt)
__device__ int   g_bsum[NB];
__device__ int   g_boff[NB];           // block offsets (exclusive)
__device__ int   g_psrc[EMAX];
__device__ float g_pw[EMAX];
__device__ double g_sum[2][CC];
__device__ double g_sumsq[2][CC];

// ---------------- merged init + feat->half conversion ----------------------
__global__ void __launch_bounds__(256) k_cvt(const float* __restrict__ feat)
{
    size_t i = (size_t)blockIdx.x * 256 + threadIdx.x;   // float4 index
    if (i < (size_t)NN * (CC / 4)) {
        float4 v = ((const float4*)feat)[i];
        __half2 h0 = __floats2half2_rn(v.x, v.y);
        __half2 h1 = __floats2half2_rn(v.z, v.w);
        uint2 p;
        p.x = *(unsigned*)&h0;
        p.y = *(unsigned*)&h1;
        ((uint2*)g_hx)[i] = p;
    }
    int j = blockIdx.x * 256 + threadIdx.x;
    if (j < NN) { g_cnt[j] = 0; g_cursor[j] = 0; }
    if (blockIdx.x == 0 && threadIdx.x < CC) {
        g_sum[0][threadIdx.x] = 0.0;  g_sumsq[0][threadIdx.x] = 0.0;
        g_sum[1][threadIdx.x] = 0.0;  g_sumsq[1][threadIdx.x] = 0.0;
    }
}

__global__ void __launch_bounds__(256) k_hist(const int* __restrict__ dst, int E)
{
    int e = blockIdx.x * 256 + threadIdx.x;
    if (e < E) atomicAdd(&g_cnt[dst[e]], 1);
}

__global__ void __launch_bounds__(256) k_scan1()
{
    __shared__ int sm[256];
    int tid = threadIdx.x;
    int i = blockIdx.x * 256 + tid;
    int c = (i < NN) ? g_cnt[i] : 0;
    sm[tid] = c;
    __syncthreads();
    #pragma unroll
    for (int off = 1; off < 256; off <<= 1) {
        int v = (tid >= off) ? sm[tid - off] : 0;
        __syncthreads();
        sm[tid] += v;
        __syncthreads();
    }
    if (i < NN) g_rowstart[i] = sm[tid] - c;       // block-LOCAL exclusive
    if (tid == 255) g_bsum[blockIdx.x] = sm[255];
}

__global__ void __launch_bounds__(512) k_scan2()
{
    __shared__ int sm[512];
    int tid = threadIdx.x;
    int v = (tid < NB) ? g_bsum[tid] : 0;
    sm[tid] = v;
    __syncthreads();
    #pragma unroll
    for (int off = 1; off < 512; off <<= 1) {
        int u = (tid >= off) ? sm[tid - off] : 0;
        __syncthreads();
        sm[tid] += u;
        __syncthreads();
    }
    if (tid < NB) g_boff[tid] = sm[tid] - v;       // exclusive block offset
}

__global__ void __launch_bounds__(256) k_fill(const int* __restrict__ src,
                                              const int* __restrict__ dst,
                                              const float* __restrict__ ew,
                                              int E)
{
    int e = blockIdx.x * 256 + threadIdx.x;
    if (e < E) {
        int d = dst[e];
        int base = g_rowstart[d] + g_boff[d >> 8];
        int slot = base + atomicAdd(&g_cursor[d], 1);
        g_psrc[slot] = src[e];
        g_pw[slot]   = ew[e];
    }
}

// ---------------- gather aggregation: warp per node ------------------------
// fp32 accumulation, single rounding to half on store into g_ah.
template<int AFF>
__global__ void __launch_bounds__(256) k_gather(int sel,
                                                const float* __restrict__ gamma,
                                                const float* __restrict__ beta)
{
    __shared__ float s_sc[CC], s_sh[CC];
    const int tid  = threadIdx.x;
    const int lane = tid & 31;

    if (AFF) {
        if (tid < CC) {
            double mean = g_sum[sel][tid]   * (1.0 / NN);
            double var  = g_sumsq[sel][tid] * (1.0 / NN) - mean * mean;
            float sc = gamma[tid] * rsqrtf((float)var + 1e-5f);
            s_sc[tid] = sc;
            s_sh[tid] = beta[tid] - (float)mean * sc;
        }
        __syncthreads();
    }

    int v = blockIdx.x * 8 + (tid >> 5);
    if (v >= NN) return;

    float4 sc4, sh4;
    if (AFF) {
        sc4 = *(const float4*)(s_sc + lane * 4);
        sh4 = *(const float4*)(s_sh + lane * 4);
    }

    const int start = g_rowstart[v] + g_boff[v >> 8];
    const int deg   = g_cnt[v];
    float4 acc = make_float4(0.f, 0.f, 0.f, 0.f);
    const __half* __restrict__ x = g_hx;

    for (int j = 0; j < deg; j++) {
        int   s0 = g_psrc[start + j];
        float w0 = g_pw[start + j];
        uint2 raw = *(const uint2*)(x + (size_t)s0 * CC + lane * 4);
        float2 f0 = __half22float2(*(__half2*)&raw.x);
        float2 f1 = __half22float2(*(__half2*)&raw.y);
        if (AFF) {
            f0.x = fmaxf(fmaf(f0.x, sc4.x, sh4.x), 0.f);
            f0.y = fmaxf(fmaf(f0.y, sc4.y, sh4.y), 0.f);
            f1.x = fmaxf(fmaf(f1.x, sc4.z, sh4.z), 0.f);
            f1.y = fmaxf(fmaf(f1.y, sc4.w, sh4.w), 0.f);
        }
        acc.x = fmaf(w0, f0.x, acc.x);
        acc.y = fmaf(w0, f0.y, acc.y);
        acc.z = fmaf(w0, f1.x, acc.z);
        acc.w = fmaf(w0, f1.y, acc.w);
    }
    __half2 o0 = __floats2half2_rn(acc.x, acc.y);
    __half2 o1 = __floats2half2_rn(acc.z, acc.w);
    uint2 p;
    p.x = *(unsigned*)&o0;
    p.y = *(unsigned*)&o1;
    *(uint2*)(g_ah + (size_t)v * CC + lane * 4) = p;
}

// ---------------- 128x128 GEMM via wmma (HMMA) with fused BN stats ---------
// A (half, g_ah) and W (fp32->half at load) in smem; fp32 accumulators;
// C stored to smem (overlaying A/B) for the stats + half-h epilogue.
#define AH_STRIDE 136                       // halfs, padded
#define CS_STRIDE 132                       // floats, padded
#define SMEM_GEMM_BYTES (69632 + 1024)      // Ah(34816)+Bh(34816) ov. Cs(67584); +csum/csq
__global__ void __launch_bounds__(256) k_gemm128(const float* __restrict__ Wg,
                                                 int sel)
{
    extern __shared__ char smraw[];
    __half* Ah   = (__half*)smraw;                    // 128 x 136 halfs
    __half* Bh   = (__half*)(smraw + 34816);          // 128 x 136 halfs
    float*  Cs   = (float*)smraw;                     // 128 x 132 floats (overlay)
    float*  csum = (float*)(smraw + 69632);           // 128
    float*  csq  = csum + 128;                        // 128

    const int tid = threadIdx.x;
    const int wid = tid >> 5;
    const int rowBase = blockIdx.x * 128;

    // load W (row-major [k][c], fp32) -> Bh half
    #pragma unroll
    for (int i = 0; i < 16; i++) {
        int idx = i * 1024 + tid * 4;          // 4 consecutive floats
        int row = idx >> 7;
        int col = idx & 127;
        float4 w4 = *(const float4*)(Wg + idx);
        __half2 h0 = __floats2half2_rn(w4.x, w4.y);
        __half2 h1 = __floats2half2_rn(w4.z, w4.w);
        uint2 p;  p.x = *(unsigned*)&h0;  p.y = *(unsigned*)&h1;
        *(uint2*)(Bh + row * AH_STRIDE + col) = p;
    }
    // load A tile (half rows from g_ah)
    #pragma unroll
    for (int i = 0; i < 16; i++) {
        int fl  = i * 256 + tid;               // uint2 index (4 halfs)
        int row = fl >> 5;
        int q   = fl & 31;
        int grow = rowBase + row;
        uint2 p = make_uint2(0u, 0u);
        if (grow < NN) p = *(const uint2*)(g_ah + (size_t)grow * CC + q * 4);
        *(uint2*)(Ah + row * AH_STRIDE + q * 4) = p;
    }
    if (tid < 128) { csum[tid] = 0.f; csq[tid] = 0.f; }
    __syncthreads();

    // warps: 2 along M (64 rows each), 4 along N (32 cols each)
    const int warp_m = wid & 1;
    const int warp_n = wid >> 1;

    wmma::fragment<wmma::accumulator, 16, 16, 16, float> cfr[4][2];
    #pragma unroll
    for (int i = 0; i < 4; i++)
        #pragma unroll
        for (int j = 0; j < 2; j++) wmma::fill_fragment(cfr[i][j], 0.0f);

    #pragma unroll
    for (int ks = 0; ks < 8; ks++) {
        wmma::fragment<wmma::matrix_a, 16, 16, 16, __half, wmma::row_major> afr[4];
        wmma::fragment<wmma::matrix_b, 16, 16, 16, __half, wmma::row_major> bfr[2];
        #pragma unroll
        for (int i = 0; i < 4; i++)
            wmma::load_matrix_sync(afr[i],
                Ah + (warp_m * 64 + i * 16) * AH_STRIDE + ks * 16, AH_STRIDE);
        #pragma unroll
        for (int j = 0; j < 2; j++)
            wmma::load_matrix_sync(bfr[j],
                Bh + (ks * 16) * AH_STRIDE + warp_n * 32 + j * 16, AH_STRIDE);
        #pragma unroll
        for (int i = 0; i < 4; i++)
            #pragma unroll
            for (int j = 0; j < 2; j++)
                wmma::mma_sync(cfr[i][j], afr[i], bfr[j], cfr[i][j]);
    }
    __syncthreads();   // all warps done reading Ah/Bh before Cs overlay

    #pragma unroll
    for (int i = 0; i < 4; i++)
        #pragma unroll
        for (int j = 0; j < 2; j++)
            wmma::store_matrix_sync(
                Cs + (warp_m * 64 + i * 16) * CS_STRIDE + warp_n * 32 + j * 16,
                cfr[i][j], CS_STRIDE, wmma::mem_row_major);
    __syncthreads();

    // epilogue: h -> g_hx (half) + BN stats, reading Cs
    const int tx = tid & 15;
    const int ty = tid >> 4;
    const int colBase = tx * 8;

    float psum[8], psq[8];
    #pragma unroll
    for (int jj = 0; jj < 8; jj++) { psum[jj] = 0.f; psq[jj] = 0.f; }

    #pragma unroll
    for (int r = 0; r < 8; r++) {
        int row  = ty * 8 + r;
        int grow = rowBase + row;
        if (grow < NN) {
            float4 v0 = *(const float4*)(Cs + row * CS_STRIDE + colBase);
            float4 v1 = *(const float4*)(Cs + row * CS_STRIDE + colBase + 4);
            __half2 h0 = __floats2half2_rn(v0.x, v0.y);
            __half2 h1 = __floats2half2_rn(v0.z, v0.w);
            __half2 h2 = __floats2half2_rn(v1.x, v1.y);
            __half2 h3 = __floats2half2_rn(v1.z, v1.w);
            uint4 p;
            p.x = *(unsigned*)&h0;  p.y = *(unsigned*)&h1;
            p.z = *(unsigned*)&h2;  p.w = *(unsigned*)&h3;
            *(uint4*)(g_hx + (size_t)grow * CC + colBase) = p;
            psum[0] += v0.x;  psq[0] += v0.x * v0.x;
            psum[1] += v0.y;  psq[1] += v0.y * v0.y;
            psum[2] += v0.z;  psq[2] += v0.z * v0.z;
            psum[3] += v0.w;  psq[3] += v0.w * v0.w;
            psum[4] += v1.x;  psq[4] += v1.x * v1.x;
            psum[5] += v1.y;  psq[5] += v1.y * v1.y;
            psum[6] += v1.z;  psq[6] += v1.z * v1.z;
            psum[7] += v1.w;  psq[7] += v1.w * v1.w;
        }
    }
    #pragma unroll
    for (int jj = 0; jj < 8; jj++) {
        atomicAdd(&csum[colBase + jj], psum[jj]);
        atomicAdd(&csq[colBase + jj],  psq[jj]);
    }
    __syncthreads();
    if (tid < 128) {
        atomicAdd(&g_sum[sel][tid],   (double)csum[tid]);
        atomicAdd(&g_sumsq[sel][tid], (double)csq[tid]);
    }
}

// ---------------- layer-3 pre-transform: z = relu(bn2(h)) @ W3 -------------
#define SMEM_PRE_FLOATS (5120 + 128 * 132 + 256)
__global__ void __launch_bounds__(256) k_pre(const float* __restrict__ W3,
                                             const float* __restrict__ gamma,
                                             const float* __restrict__ beta)
{
    extern __shared__ float sm[];
    float* Ws   = sm;                 // 128*40
    float* As   = sm + 5120;          // 128*132
    float* s_sc = As + 128 * 132;     // 128
    float* s_sh = s_sc + 128;         // 128

    const int tid = threadIdx.x;
    const int rowBase = blockIdx.x * 128;

    if (tid < CC) {
        double mean = g_sum[1][tid]   * (1.0 / NN);
        double var  = g_sumsq[1][tid] * (1.0 / NN) - mean * mean;
        float sc = gamma[tid] * rsqrtf((float)var + 1e-5f);
        s_sc[tid] = sc;
        s_sh[tid] = beta[tid] - (float)mean * sc;
    }
    for (int i = tid; i < 5120; i += 256) Ws[i] = W3[i];
    __syncthreads();

    #pragma unroll
    for (int i = 0; i < 16; i++) {
        int fl  = i * 256 + tid;       // uint2 index within tile
        int row = fl >> 5;
        int q   = fl & 31;             // 4-channel group
        int grow = rowBase + row;
        float f[4] = {0.f, 0.f, 0.f, 0.f};
        if (grow < NN) {
            uint2 raw = *(const uint2*)(g_hx + (size_t)grow * CC + q * 4);
            float2 a = __half22float2(*(__half2*)&raw.x);
            float2 b = __half22float2(*(__half2*)&raw.y);
            f[0] = fmaxf(fmaf(a.x, s_sc[q * 4 + 0], s_sh[q * 4 + 0]), 0.f);
            f[1] = fmaxf(fmaf(a.y, s_sc[q * 4 + 1], s_sh[q * 4 + 1]), 0.f);
            f[2] = fmaxf(fmaf(b.x, s_sc[q * 4 + 2], s_sh[q * 4 + 2]), 0.f);
            f[3] = fmaxf(fmaf(b.y, s_sc[q * 4 + 3], s_sh[q * 4 + 3]), 0.f);
        }
        *(float4*)(As + row * 132 + q * 4) = make_float4(f[0], f[1], f[2], f[3]);
    }
    __syncthreads();

    const int cg = tid & 7;    // 8 col groups x 5 cols
    const int rg = tid >> 3;   // 32 row groups x 4 rows
    float acc[4][5];
    #pragma unroll
    for (int r = 0; r < 4; r++)
        #pragma unroll
        for (int j = 0; j < 5; j++) acc[r][j] = 0.f;

    #pragma unroll 2
    for (int k = 0; k < 128; k++) {
        float b[5];
        #pragma unroll
        for (int j = 0; j < 5; j++) b[j] = Ws[k * 40 + cg * 5 + j];
        #pragma unroll
        for (int r = 0; r < 4; r++) {
            float a = As[(rg * 4 + r) * 132 + k];
            #pragma unroll
            for (int j = 0; j < 5; j++) acc[r][j] = fmaf(a, b[j], acc[r][j]);
        }
    }
    #pragma unroll
    for (int r = 0; r < 4; r++) {
        int grow = rowBase + rg * 4 + r;
        if (grow < NN) {
            #pragma unroll
            for (int j = 0; j < 5; j++)
                g_z[(size_t)grow * 40 + cg * 5 + j] = acc[r][j];
        }
    }
}

// ---------------- layer-3 aggregation over 40 channels, + bias, -> out -----
__global__ void __launch_bounds__(256) k_gather_out(const float* __restrict__ b3,
                                                    float* __restrict__ out)
{
    int v = blockIdx.x * 8 + (threadIdx.x >> 5);
    if (v >= NN) return;
    const int lane = threadIdx.x & 31;

    const int start = g_rowstart[v] + g_boff[v >> 8];
    const int deg   = g_cnt[v];
    const float* __restrict__ z = g_z;

    float2 acc = make_float2(0.f, 0.f);
    for (int j = 0; j < deg; j++) {
        int   s0 = g_psrc[start + j];
        float w0 = g_pw[start + j];
        if (lane < 20) {
            float2 zz = *(const float2*)(z + (size_t)s0 * 40 + lane * 2);
            acc.x = fmaf(w0, zz.x, acc.x);
            acc.y = fmaf(w0, zz.y, acc.y);
        }
    }
    if (lane < 20) {
        float2 bb = *(const float2*)(b3 + lane * 2);
        float2 o;
        o.x = acc.x + bb.x;
        o.y = acc.y + bb.y;
        *(float2*)(out + (size_t)v * 40 + lane * 2) = o;
    }
}

// ---------------- launch ---------------------------------------------------
extern "C" void kernel_launch(void* const* d_in, const int* in_sizes, int n_in,
                              void* d_out, int out_size)
{
    const float* feat   = (const float*)d_in[0];
    const int*   src    = (const int*)  d_in[1];
    const int*   dst    = (const int*)  d_in[2];
    const float* ew     = (const float*)d_in[3];
    const float* W1     = (const float*)d_in[4];
    const float* W2     = (const float*)d_in[5];
    const float* W3     = (const float*)d_in[6];
    const float* b3     = (const float*)d_in[7];
    const float* gamma1 = (const float*)d_in[8];
    const float* beta1  = (const float*)d_in[9];
    const float* gamma2 = (const float*)d_in[10];
    const float* beta2  = (const float*)d_in[11];
    float* out = (float*)d_out;
    const int E = in_sizes[1];

    const int smemGemm = SMEM_GEMM_BYTES;          // 70656 B
    const int smemPre  = SMEM_PRE_FLOATS * 4;
    cudaFuncSetAttribute(k_gemm128, cudaFuncAttributeMaxDynamicSharedMemorySize, smemGemm);
    cudaFuncSetAttribute(k_pre,     cudaFuncAttributeMaxDynamicSharedMemorySize, smemPre);

    const int egrid = (E + 255) / 256;
    const int ggrid = (NN + 127) / 128;
    const int agrid = (NN + 7) / 8;
    const int cgrid = (NN * (CC / 4) + 255) / 256;

    // ---- CSR build ----
    k_cvt  <<<cgrid, 256>>>(feat);
    k_hist <<<egrid, 256>>>(dst, E);
    k_scan1<<<NB, 256>>>();
    k_scan2<<<1, 512>>>();
    k_fill <<<egrid, 256>>>(src, dst, ew, E);

    // ---- layer 1 ----
    k_gather<0><<<agrid, 256>>>(0, nullptr, nullptr);
    k_gemm128<<<ggrid, 256, smemGemm>>>(W1, 0);

    // ---- layer 2 (BN1+ReLU fused into gather) ----
    k_gather<1><<<agrid, 256>>>(0, gamma1, beta1);
    k_gemm128<<<ggrid, 256, smemGemm>>>(W2, 1);

    // ---- layer 3: pre-transform (BN2+ReLU+W3), then 40-ch aggregation ----
    k_pre<<<ggrid, 256, smemPre>>>(W3, gamma2, beta2);
    k_gather_out<<<agrid, 256>>>(b3, out);
}

// round 14
// speedup vs baseline: 3.4473x; 1.1040x over previous
#include <cuda_runtime.h>
#include <cuda_fp16.h>
#include <mma.h>
#include <cstdint>

using namespace nvcuda;

#define NN   100000
#define CC   128
#define EMAX 1600000
#define NB   ((NN + 255) / 256)        // 391 scan blocks

// ---------------- scratch (static device globals) --------------------------
__device__ __align__(16) __half g_ah[(size_t)NN * CC];   // half agg buffer
__device__ __align__(16) __half g_zh[(size_t)NN * 40];   // layer-3 z (half)
__device__ __align__(16) __half g_hx[(size_t)NN * CC];   // half features
__device__ int   g_cnt[NN];
__device__ int   g_rowstart[NN];       // block-local exclusive prefix
__device__ int   g_cursor[NN];         // fill counters (zeroed in k_cvt)
__device__ int   g_bsum[NB];
__device__ int   g_boff[NB];           // block offsets (exclusive)
__device__ int   g_psrc[EMAX];
__device__ float g_pw[EMAX];
__device__ double g_sum[2][CC];
__device__ double g_sumsq[2][CC];

// ---------------- merged init + feat->half conversion ----------------------
__global__ void __launch_bounds__(256) k_cvt(const float* __restrict__ feat)
{
    size_t i = (size_t)blockIdx.x * 256 + threadIdx.x;   // float4 index
    if (i < (size_t)NN * (CC / 4)) {
        float4 v = ((const float4*)feat)[i];
        __half2 h0 = __floats2half2_rn(v.x, v.y);
        __half2 h1 = __floats2half2_rn(v.z, v.w);
        uint2 p;
        p.x = *(unsigned*)&h0;
        p.y = *(unsigned*)&h1;
        ((uint2*)g_hx)[i] = p;
    }
    int j = blockIdx.x * 256 + threadIdx.x;
    if (j < NN) { g_cnt[j] = 0; g_cursor[j] = 0; }
    if (blockIdx.x == 0 && threadIdx.x < CC) {
        g_sum[0][threadIdx.x] = 0.0;  g_sumsq[0][threadIdx.x] = 0.0;
        g_sum[1][threadIdx.x] = 0.0;  g_sumsq[1][threadIdx.x] = 0.0;
    }
}

__global__ void __launch_bounds__(256) k_hist(const int* __restrict__ dst, int E)
{
    int e = blockIdx.x * 256 + threadIdx.x;
    if (e < E) atomicAdd(&g_cnt[dst[e]], 1);
}

__global__ void __launch_bounds__(256) k_scan1()
{
    __shared__ int sm[256];
    int tid = threadIdx.x;
    int i = blockIdx.x * 256 + tid;
    int c = (i < NN) ? g_cnt[i] : 0;
    sm[tid] = c;
    __syncthreads();
    #pragma unroll
    for (int off = 1; off < 256; off <<= 1) {
        int v = (tid >= off) ? sm[tid - off] : 0;
        __syncthreads();
        sm[tid] += v;
        __syncthreads();
    }
    if (i < NN) g_rowstart[i] = sm[tid] - c;       // block-LOCAL exclusive
    if (tid == 255) g_bsum[blockIdx.x] = sm[255];
}

__global__ void __launch_bounds__(512) k_scan2()
{
    __shared__ int sm[512];
    int tid = threadIdx.x;
    int v = (tid < NB) ? g_bsum[tid] : 0;
    sm[tid] = v;
    __syncthreads();
    #pragma unroll
    for (int off = 1; off < 512; off <<= 1) {
        int u = (tid >= off) ? sm[tid - off] : 0;
        __syncthreads();
        sm[tid] += u;
        __syncthreads();
    }
    if (tid < NB) g_boff[tid] = sm[tid] - v;       // exclusive block offset
}

__global__ void __launch_bounds__(256) k_fill(const int* __restrict__ src,
                                              const int* __restrict__ dst,
                                              const float* __restrict__ ew,
                                              int E)
{
    int e = blockIdx.x * 256 + threadIdx.x;
    if (e < E) {
        int d = dst[e];
        int base = g_rowstart[d] + g_boff[d >> 8];
        int slot = base + atomicAdd(&g_cursor[d], 1);
        g_psrc[slot] = src[e];
        g_pw[slot]   = ew[e];
    }
}

// ---------------- gather aggregation: warp per node ------------------------
// fp32 accumulation, single rounding to half on store into g_ah.
template<int AFF>
__global__ void __launch_bounds__(256) k_gather(int sel,
                                                const float* __restrict__ gamma,
                                                const float* __restrict__ beta)
{
    __shared__ float s_sc[CC], s_sh[CC];
    const int tid  = threadIdx.x;
    const int lane = tid & 31;

    if (AFF) {
        if (tid < CC) {
            double mean = g_sum[sel][tid]   * (1.0 / NN);
            double var  = g_sumsq[sel][tid] * (1.0 / NN) - mean * mean;
            float sc = gamma[tid] * rsqrtf((float)var + 1e-5f);
            s_sc[tid] = sc;
            s_sh[tid] = beta[tid] - (float)mean * sc;
        }
        __syncthreads();
    }

    int v = blockIdx.x * 8 + (tid >> 5);
    if (v >= NN) return;

    float4 sc4, sh4;
    if (AFF) {
        sc4 = *(const float4*)(s_sc + lane * 4);
        sh4 = *(const float4*)(s_sh + lane * 4);
    }

    const int start = g_rowstart[v] + g_boff[v >> 8];
    const int deg   = g_cnt[v];
    float4 acc = make_float4(0.f, 0.f, 0.f, 0.f);
    const __half* __restrict__ x = g_hx;

    for (int j = 0; j < deg; j++) {
        int   s0 = g_psrc[start + j];
        float w0 = g_pw[start + j];
        uint2 raw = *(const uint2*)(x + (size_t)s0 * CC + lane * 4);
        float2 f0 = __half22float2(*(__half2*)&raw.x);
        float2 f1 = __half22float2(*(__half2*)&raw.y);
        if (AFF) {
            f0.x = fmaxf(fmaf(f0.x, sc4.x, sh4.x), 0.f);
            f0.y = fmaxf(fmaf(f0.y, sc4.y, sh4.y), 0.f);
            f1.x = fmaxf(fmaf(f1.x, sc4.z, sh4.z), 0.f);
            f1.y = fmaxf(fmaf(f1.y, sc4.w, sh4.w), 0.f);
        }
        acc.x = fmaf(w0, f0.x, acc.x);
        acc.y = fmaf(w0, f0.y, acc.y);
        acc.z = fmaf(w0, f1.x, acc.z);
        acc.w = fmaf(w0, f1.y, acc.w);
    }
    __half2 o0 = __floats2half2_rn(acc.x, acc.y);
    __half2 o1 = __floats2half2_rn(acc.z, acc.w);
    uint2 p;
    p.x = *(unsigned*)&o0;
    p.y = *(unsigned*)&o1;
    *(uint2*)(g_ah + (size_t)v * CC + lane * 4) = p;
}

// ---------------- 128x128 GEMM via wmma (HMMA) with fused BN stats ---------
#define AH_STRIDE 136                       // halfs, padded
#define CS_STRIDE 132                       // floats, padded
#define SMEM_GEMM_BYTES (69632 + 1024)      // Ah(34816)+Bh(34816) ov. Cs(67584); +csum/csq
__global__ void __launch_bounds__(256) k_gemm128(const float* __restrict__ Wg,
                                                 int sel)
{
    extern __shared__ char smraw[];
    __half* Ah   = (__half*)smraw;                    // 128 x 136 halfs
    __half* Bh   = (__half*)(smraw + 34816);          // 128 x 136 halfs
    float*  Cs   = (float*)smraw;                     // 128 x 132 floats (overlay)
    float*  csum = (float*)(smraw + 69632);           // 128
    float*  csq  = csum + 128;                        // 128

    const int tid = threadIdx.x;
    const int wid = tid >> 5;
    const int rowBase = blockIdx.x * 128;

    // load W (row-major [k][c], fp32) -> Bh half
    #pragma unroll
    for (int i = 0; i < 16; i++) {
        int idx = i * 1024 + tid * 4;          // 4 consecutive floats
        int row = idx >> 7;
        int col = idx & 127;
        float4 w4 = *(const float4*)(Wg + idx);
        __half2 h0 = __floats2half2_rn(w4.x, w4.y);
        __half2 h1 = __floats2half2_rn(w4.z, w4.w);
        uint2 p;  p.x = *(unsigned*)&h0;  p.y = *(unsigned*)&h1;
        *(uint2*)(Bh + row * AH_STRIDE + col) = p;
    }
    // load A tile (half rows from g_ah)
    #pragma unroll
    for (int i = 0; i < 16; i++) {
        int fl  = i * 256 + tid;               // uint2 index (4 halfs)
        int row = fl >> 5;
        int q   = fl & 31;
        int grow = rowBase + row;
        uint2 p = make_uint2(0u, 0u);
        if (grow < NN) p = *(const uint2*)(g_ah + (size_t)grow * CC + q * 4);
        *(uint2*)(Ah + row * AH_STRIDE + q * 4) = p;
    }
    if (tid < 128) { csum[tid] = 0.f; csq[tid] = 0.f; }
    __syncthreads();

    // warps: 2 along M (64 rows each), 4 along N (32 cols each)
    const int warp_m = wid & 1;
    const int warp_n = wid >> 1;

    wmma::fragment<wmma::accumulator, 16, 16, 16, float> cfr[4][2];
    #pragma unroll
    for (int i = 0; i < 4; i++)
        #pragma unroll
        for (int j = 0; j < 2; j++) wmma::fill_fragment(cfr[i][j], 0.0f);

    #pragma unroll
    for (int ks = 0; ks < 8; ks++) {
        wmma::fragment<wmma::matrix_a, 16, 16, 16, __half, wmma::row_major> afr[4];
        wmma::fragment<wmma::matrix_b, 16, 16, 16, __half, wmma::row_major> bfr[2];
        #pragma unroll
        for (int i = 0; i < 4; i++)
            wmma::load_matrix_sync(afr[i],
                Ah + (warp_m * 64 + i * 16) * AH_STRIDE + ks * 16, AH_STRIDE);
        #pragma unroll
        for (int j = 0; j < 2; j++)
            wmma::load_matrix_sync(bfr[j],
                Bh + (ks * 16) * AH_STRIDE + warp_n * 32 + j * 16, AH_STRIDE);
        #pragma unroll
        for (int i = 0; i < 4; i++)
            #pragma unroll
            for (int j = 0; j < 2; j++)
                wmma::mma_sync(cfr[i][j], afr[i], bfr[j], cfr[i][j]);
    }
    __syncthreads();   // all warps done reading Ah/Bh before Cs overlay

    #pragma unroll
    for (int i = 0; i < 4; i++)
        #pragma unroll
        for (int j = 0; j < 2; j++)
            wmma::store_matrix_sync(
                Cs + (warp_m * 64 + i * 16) * CS_STRIDE + warp_n * 32 + j * 16,
                cfr[i][j], CS_STRIDE, wmma::mem_row_major);
    __syncthreads();

    // epilogue: h -> g_hx (half) + BN stats, reading Cs
    const int tx = tid & 15;
    const int ty = tid >> 4;
    const int colBase = tx * 8;

    float psum[8], psq[8];
    #pragma unroll
    for (int jj = 0; jj < 8; jj++) { psum[jj] = 0.f; psq[jj] = 0.f; }

    #pragma unroll
    for (int r = 0; r < 8; r++) {
        int row  = ty * 8 + r;
        int grow = rowBase + row;
        if (grow < NN) {
            float4 v0 = *(const float4*)(Cs + row * CS_STRIDE + colBase);
            float4 v1 = *(const float4*)(Cs + row * CS_STRIDE + colBase + 4);
            __half2 h0 = __floats2half2_rn(v0.x, v0.y);
            __half2 h1 = __floats2half2_rn(v0.z, v0.w);
            __half2 h2 = __floats2half2_rn(v1.x, v1.y);
            __half2 h3 = __floats2half2_rn(v1.z, v1.w);
            uint4 p;
            p.x = *(unsigned*)&h0;  p.y = *(unsigned*)&h1;
            p.z = *(unsigned*)&h2;  p.w = *(unsigned*)&h3;
            *(uint4*)(g_hx + (size_t)grow * CC + colBase) = p;
            psum[0] += v0.x;  psq[0] += v0.x * v0.x;
            psum[1] += v0.y;  psq[1] += v0.y * v0.y;
            psum[2] += v0.z;  psq[2] += v0.z * v0.z;
            psum[3] += v0.w;  psq[3] += v0.w * v0.w;
            psum[4] += v1.x;  psq[4] += v1.x * v1.x;
            psum[5] += v1.y;  psq[5] += v1.y * v1.y;
            psum[6] += v1.z;  psq[6] += v1.z * v1.z;
            psum[7] += v1.w;  psq[7] += v1.w * v1.w;
        }
    }
    #pragma unroll
    for (int jj = 0; jj < 8; jj++) {
        atomicAdd(&csum[colBase + jj], psum[jj]);
        atomicAdd(&csq[colBase + jj],  psq[jj]);
    }
    __syncthreads();
    if (tid < 128) {
        atomicAdd(&g_sum[sel][tid],   (double)csum[tid]);
        atomicAdd(&g_sumsq[sel][tid], (double)csq[tid]);
    }
}

// ---------------- layer-3 pre-transform via wmma: z = relu(bn2(h)) @ W3 ----
// A = relu(bn2(h)) (half, built in smem); B = W3 padded 40->48 cols (half);
// fp32 accumulators; z written as HALF to g_zh.
#define PW_BSTRIDE 56          // halfs
#define PW_CSTRIDE 52          // floats
#define SMEM_PRE_BYTES (34816 + 14336 + 26624)   // Ah + Bw + Cs = 75776
__global__ void __launch_bounds__(256) k_pre(const float* __restrict__ W3,
                                             const float* __restrict__ gamma,
                                             const float* __restrict__ beta)
{
    extern __shared__ char smraw[];
    __half* Ah = (__half*)smraw;                  // 128 x 136 halfs
    __half* Bw = (__half*)(smraw + 34816);        // 128 x 56 halfs (zero-padded)
    float*  Cs = (float*)(smraw + 49152);         // 128 x 52 floats
    __shared__ float s_sc[CC], s_sh[CC];

    const int tid = threadIdx.x;
    const int wid = tid >> 5;
    const int rowBase = blockIdx.x * 128;

    if (tid < CC) {
        double mean = g_sum[1][tid]   * (1.0 / NN);
        double var  = g_sumsq[1][tid] * (1.0 / NN) - mean * mean;
        float sc = gamma[tid] * rsqrtf((float)var + 1e-5f);
        s_sc[tid] = sc;
        s_sh[tid] = beta[tid] - (float)mean * sc;
    }
    // zero Bw (padding cols must be 0)
    for (int i = tid; i < 128 * PW_BSTRIDE / 2; i += 256)
        ((unsigned*)Bw)[i] = 0u;
    __syncthreads();

    // fill Bw from W3 [128 x 40] fp32
    for (int i = tid; i < 5120; i += 256) {
        int row = i / 40, col = i - row * 40;
        Bw[row * PW_BSTRIDE + col] = __float2half_rn(W3[i]);
    }
    // build A tile: relu(bn2(h)) -> half
    #pragma unroll
    for (int i = 0; i < 16; i++) {
        int fl  = i * 256 + tid;       // uint2 index within tile
        int row = fl >> 5;
        int q   = fl & 31;             // 4-channel group
        int grow = rowBase + row;
        uint2 p = make_uint2(0u, 0u);
        if (grow < NN) {
            uint2 raw = *(const uint2*)(g_hx + (size_t)grow * CC + q * 4);
            float2 a = __half22float2(*(__half2*)&raw.x);
            float2 b = __half22float2(*(__half2*)&raw.y);
            float f0 = fmaxf(fmaf(a.x, s_sc[q * 4 + 0], s_sh[q * 4 + 0]), 0.f);
            float f1 = fmaxf(fmaf(a.y, s_sc[q * 4 + 1], s_sh[q * 4 + 1]), 0.f);
            float f2 = fmaxf(fmaf(b.x, s_sc[q * 4 + 2], s_sh[q * 4 + 2]), 0.f);
            float f3 = fmaxf(fmaf(b.y, s_sc[q * 4 + 3], s_sh[q * 4 + 3]), 0.f);
            __half2 h0 = __floats2half2_rn(f0, f1);
            __half2 h1 = __floats2half2_rn(f2, f3);
            p.x = *(unsigned*)&h0;  p.y = *(unsigned*)&h1;
        }
        *(uint2*)(Ah + row * AH_STRIDE + q * 4) = p;
    }
    __syncthreads();

    // wmma: warp w handles rows [w*16, w*16+16), all 48 cols (3 fragments)
    wmma::fragment<wmma::accumulator, 16, 16, 16, float> cfr[3];
    #pragma unroll
    for (int j = 0; j < 3; j++) wmma::fill_fragment(cfr[j], 0.0f);

    #pragma unroll
    for (int ks = 0; ks < 8; ks++) {
        wmma::fragment<wmma::matrix_a, 16, 16, 16, __half, wmma::row_major> afr;
        wmma::load_matrix_sync(afr, Ah + (wid * 16) * AH_STRIDE + ks * 16, AH_STRIDE);
        #pragma unroll
        for (int j = 0; j < 3; j++) {
            wmma::fragment<wmma::matrix_b, 16, 16, 16, __half, wmma::row_major> bfr;
            wmma::load_matrix_sync(bfr, Bw + (ks * 16) * PW_BSTRIDE + j * 16, PW_BSTRIDE);
            wmma::mma_sync(cfr[j], afr, bfr, cfr[j]);
        }
    }
    #pragma unroll
    for (int j = 0; j < 3; j++)
        wmma::store_matrix_sync(Cs + (wid * 16) * PW_CSTRIDE + j * 16,
                                cfr[j], PW_CSTRIDE, wmma::mem_row_major);
    __syncthreads();

    // epilogue: thread t -> row t/2, cols (t&1)*20 .. +20, write half z
    {
        int row  = tid >> 1;
        int c0   = (tid & 1) * 20;
        int grow = rowBase + row;
        if (grow < NN) {
            const float* cr = Cs + row * PW_CSTRIDE + c0;
            __half* zr = g_zh + (size_t)grow * 40 + c0;
            #pragma unroll
            for (int c = 0; c < 20; c += 2) {
                __half2 h = __floats2half2_rn(cr[c], cr[c + 1]);
                *(unsigned*)(zr + c) = *(unsigned*)&h;
            }
        }
    }
}

// ---------------- layer-3 aggregation over 40 half channels, + bias --------
__global__ void __launch_bounds__(256) k_gather_out(const float* __restrict__ b3,
                                                    float* __restrict__ out)
{
    int v = blockIdx.x * 8 + (threadIdx.x >> 5);
    if (v >= NN) return;
    const int lane = threadIdx.x & 31;

    const int start = g_rowstart[v] + g_boff[v >> 8];
    const int deg   = g_cnt[v];
    const __half* __restrict__ z = g_zh;

    float2 acc = make_float2(0.f, 0.f);
    for (int j = 0; j < deg; j++) {
        int   s0 = g_psrc[start + j];
        float w0 = g_pw[start + j];
        if (lane < 20) {
            unsigned raw = *(const unsigned*)(z + (size_t)s0 * 40 + lane * 2);
            float2 zz = __half22float2(*(__half2*)&raw);
            acc.x = fmaf(w0, zz.x, acc.x);
            acc.y = fmaf(w0, zz.y, acc.y);
        }
    }
    if (lane < 20) {
        float2 bb = *(const float2*)(b3 + lane * 2);
        float2 o;
        o.x = acc.x + bb.x;
        o.y = acc.y + bb.y;
        *(float2*)(out + (size_t)v * 40 + lane * 2) = o;
    }
}

// ---------------- launch ---------------------------------------------------
extern "C" void kernel_launch(void* const* d_in, const int* in_sizes, int n_in,
                              void* d_out, int out_size)
{
    const float* feat   = (const float*)d_in[0];
    const int*   src    = (const int*)  d_in[1];
    const int*   dst    = (const int*)  d_in[2];
    const float* ew     = (const float*)d_in[3];
    const float* W1     = (const float*)d_in[4];
    const float* W2     = (const float*)d_in[5];
    const float* W3     = (const float*)d_in[6];
    const float* b3     = (const float*)d_in[7];
    const float* gamma1 = (const float*)d_in[8];
    const float* beta1  = (const float*)d_in[9];
    const float* gamma2 = (const float*)d_in[10];
    const float* beta2  = (const float*)d_in[11];
    float* out = (float*)d_out;
    const int E = in_sizes[1];

    cudaFuncSetAttribute(k_gemm128, cudaFuncAttributeMaxDynamicSharedMemorySize, SMEM_GEMM_BYTES);
    cudaFuncSetAttribute(k_pre,     cudaFuncAttributeMaxDynamicSharedMemorySize, SMEM_PRE_BYTES);

    const int egrid = (E + 255) / 256;
    const int ggrid = (NN + 127) / 128;
    const int agrid = (NN + 7) / 8;
    const int cgrid = (NN * (CC / 4) + 255) / 256;

    // ---- CSR build ----
    k_cvt  <<<cgrid, 256>>>(feat);
    k_hist <<<egrid, 256>>>(dst, E);
    k_scan1<<<NB, 256>>>();
    k_scan2<<<1, 512>>>();
    k_fill <<<egrid, 256>>>(src, dst, ew, E);

    // ---- layer 1 ----
    k_gather<0><<<agrid, 256>>>(0, nullptr, nullptr);
    k_gemm128<<<ggrid, 256, SMEM_GEMM_BYTES>>>(W1, 0);

    // ---- layer 2 (BN1+ReLU fused into gather) ----
    k_gather<1><<<agrid, 256>>>(0, gamma1, beta1);
    k_gemm128<<<ggrid, 256, SMEM_GEMM_BYTES>>>(W2, 1);

    // ---- layer 3: wmma pre-transform (BN2+ReLU+W3), then 40-ch gather ----
    k_pre<<<ggrid, 256, SMEM_PRE_BYTES>>>(W3, gamma2, beta2);
    k_gather_out<<<agrid, 256>>>(b3, out);
}